// round 7
// baseline (speedup 1.0000x reference)
#include <cuda_runtime.h>
#include <cuda_bf16.h>
#include <math.h>

// Problem constants
#define HID    1024
#define VOCAB  32000
#define BATCH  8
#define SEQ    512
#define INDIM  768
#define MROWS  (BATCH*SEQ)      // 4096
#define GATES  (3*HID)          // 3072

// ---------------- scratch (no allocation allowed -> device globals) -----------
__device__ float g_h0[2*BATCH*HID];
__device__ float g_hA[BATCH*HID];
__device__ float g_hB[BATCH*HID];
__device__ float g_xg[(size_t)MROWS*GATES];
__device__ float g_y0[(size_t)MROWS*HID];
__device__ float g_y1[(size_t)MROWS*HID];
// hierarchical barrier state (monotonic counters, no resets)
__device__ unsigned int          g_leaf[8*32];   // 8 counters, 128B apart
__device__ unsigned int          g_root = 0;
__device__ volatile unsigned int g_gen  = 0;

// ---------------- h0: global context + c2h projection --------------------------
__global__ void h0_kernel(const float* __restrict__ concepts,
                          const float* __restrict__ c2h_w,
                          const float* __restrict__ c2h_b)
{
    __shared__ float ctx[INDIM];
    int b = blockIdx.x, tid = threadIdx.x;
    for (int d = tid; d < INDIM; d += blockDim.x) {
        float s = 0.f;
        #pragma unroll
        for (int n = 0; n < 16; n++) s += concepts[(b*16 + n)*INDIM + d];
        ctx[d] = s * (1.0f/16.0f);
    }
    __syncthreads();
    for (int k = tid; k < 2*HID; k += blockDim.x) {
        const float* w = c2h_w + (size_t)k*INDIM;
        float acc = 0.f;
        #pragma unroll 4
        for (int d = 0; d < INDIM; d += 4) {
            acc += ctx[d+0]*w[d+0] + ctx[d+1]*w[d+1]
                 + ctx[d+2]*w[d+2] + ctx[d+3]*w[d+3];
        }
        acc += c2h_b[k];
        int l = k >> 10, j = k & (HID-1);
        g_h0[(l*BATCH + b)*HID + j] = acc;
    }
}

// ---------------- bf16x3 tensor-core GEMM, 2 CTAs/SM ---------------------------
// C[M,N] = A[M,K] * B[N,K]^T + bias[N], near-fp32 via bf16 hi/lo split (3 mma
// passes). Tile 128(M)x64(N), BK=32, 256 threads (8 warps, 4m x 2n, warp 32x32),
// mma.m16n8k16. Smem 60KB/CTA double-buffered -> 2 CTAs/SM (regs capped 128).

#define GLDW  20                 // b32 words per row (16 data + 4 pad)
#define GTA   (128*GLDW)         // A tile words (2560)
#define GTB   (64*GLDW)          // B tile words (1280)
#define GBUF  (2*GTA + 2*GTB)    // words per buffer {Ah,Al,Bh,Bl} = 7680
#define GSMEM (2*GBUF*4)         // 61440 bytes

__device__ __forceinline__ unsigned pack_bf2(float a, float b)
{
    __nv_bfloat162 t = __floats2bfloat162_rn(a, b);
    return *reinterpret_cast<unsigned*>(&t);
}

__device__ __forceinline__ void split_pair(float x, float y,
                                           unsigned& hi, unsigned& lo)
{
    hi = pack_bf2(x, y);
    __nv_bfloat162 hh = *reinterpret_cast<__nv_bfloat162*>(&hi);
    lo = pack_bf2(x - __bfloat162float(hh.x), y - __bfloat162float(hh.y));
}

__device__ __forceinline__ void mma_bf16(float* d, const unsigned* a, const unsigned* b)
{
    asm volatile(
        "mma.sync.aligned.m16n8k16.row.col.f32.bf16.bf16.f32 "
        "{%0,%1,%2,%3},{%4,%5,%6,%7},{%8,%9},{%0,%1,%2,%3};"
        : "+f"(d[0]), "+f"(d[1]), "+f"(d[2]), "+f"(d[3])
        : "r"(a[0]), "r"(a[1]), "r"(a[2]), "r"(a[3]), "r"(b[0]), "r"(b[1]));
}

template<bool GATHER>
__global__ void __launch_bounds__(256, 2)
gemm_bf16x3(const float* __restrict__ A, const float* __restrict__ B,
            const float* __restrict__ bias, float* __restrict__ C,
            const int* __restrict__ gidx, int M, int N, int K)
{
    extern __shared__ unsigned sm[];
    const int tid = threadIdx.x;
    const int l   = tid & 31;
    const int wid = tid >> 5;
    const int wm  = (wid & 3) * 32;
    const int wn  = (wid >> 2) * 32;
    const int bm  = blockIdx.x * 128;
    const int bn  = blockIdx.y * 64;
    const int g   = l >> 2;         // 0..7
    const int t   = l & 3;          // 0..3

    // A loader: 1024 float4 over 256 threads (4 each); B: 512 float4 (2 each)
    int aploc[4], bploc[2];
    const float* aptr[4];
    const float* bptr[2];
    #pragma unroll
    for (int u = 0; u < 4; u++) {
        int f    = tid + u*256;
        int row  = f >> 3;
        int kf   = (f & 7) << 2;
        aploc[u] = row*GLDW + ((f & 7) << 1);
        int ar   = GATHER ? gidx[bm + row] : (bm + row);
        aptr[u]  = A + (size_t)ar*K + kf;
    }
    #pragma unroll
    for (int u = 0; u < 2; u++) {
        int f    = tid + u*256;
        int row  = f >> 3;
        int kf   = (f & 7) << 2;
        bploc[u] = row*GLDW + ((f & 7) << 1);
        bptr[u]  = B + (size_t)(bn + row)*K + kf;
    }

    float acc[2][4][4];
    #pragma unroll
    for (int i = 0; i < 2; i++)
        #pragma unroll
        for (int j = 0; j < 4; j++)
            #pragma unroll
            for (int r = 0; r < 4; r++) acc[i][j][r] = 0.f;

    float4 va[4], vb[2];
    auto gload = [&](int kt) {
        #pragma unroll
        for (int u = 0; u < 4; u++)
            va[u] = *reinterpret_cast<const float4*>(aptr[u] + kt*32);
        #pragma unroll
        for (int u = 0; u < 2; u++)
            vb[u] = *reinterpret_cast<const float4*>(bptr[u] + kt*32);
    };
    auto sstore = [&](int buf) {
        unsigned* Ah = sm + buf*GBUF;
        unsigned* Al = Ah + GTA;
        unsigned* Bh = Al + GTA;
        unsigned* Bl = Bh + GTB;
        #pragma unroll
        for (int u = 0; u < 4; u++) {
            unsigned h0, l0, h1, l1;
            split_pair(va[u].x, va[u].y, h0, l0);
            split_pair(va[u].z, va[u].w, h1, l1);
            Ah[aploc[u]] = h0; Ah[aploc[u]+1] = h1;
            Al[aploc[u]] = l0; Al[aploc[u]+1] = l1;
        }
        #pragma unroll
        for (int u = 0; u < 2; u++) {
            unsigned h0, l0, h1, l1;
            split_pair(vb[u].x, vb[u].y, h0, l0);
            split_pair(vb[u].z, vb[u].w, h1, l1);
            Bh[bploc[u]] = h0; Bh[bploc[u]+1] = h1;
            Bl[bploc[u]] = l0; Bl[bploc[u]+1] = l1;
        }
    };

    const int nk = K / 32;
    gload(0); sstore(0); __syncthreads();

    for (int kt = 0; kt < nk; kt++) {
        int cur = kt & 1;
        if (kt + 1 < nk) gload(kt + 1);

        const unsigned* Ah = sm + cur*GBUF;
        const unsigned* Al = Ah + GTA;
        const unsigned* Bh = Al + GTA;
        const unsigned* Bl = Bh + GTB;

        #pragma unroll
        for (int kh = 0; kh < 2; kh++) {
            const int bp = kh * 8;
            unsigned ah[2][4], al[2][4], bh[4][2], bl[4][2];
            #pragma unroll
            for (int mf = 0; mf < 2; mf++) {
                int r0 = (wm + mf*16 + g)*GLDW + bp + t;
                ah[mf][0] = Ah[r0];
                ah[mf][1] = Ah[r0 + 8*GLDW];
                ah[mf][2] = Ah[r0 + 4];
                ah[mf][3] = Ah[r0 + 8*GLDW + 4];
                al[mf][0] = Al[r0];
                al[mf][1] = Al[r0 + 8*GLDW];
                al[mf][2] = Al[r0 + 4];
                al[mf][3] = Al[r0 + 8*GLDW + 4];
            }
            #pragma unroll
            for (int nf = 0; nf < 4; nf++) {
                int c0 = (wn + nf*8 + g)*GLDW + bp + t;
                bh[nf][0] = Bh[c0];
                bh[nf][1] = Bh[c0 + 4];
                bl[nf][0] = Bl[c0];
                bl[nf][1] = Bl[c0 + 4];
            }
            #pragma unroll
            for (int mf = 0; mf < 2; mf++)
                #pragma unroll
                for (int nf = 0; nf < 4; nf++) {
                    mma_bf16(acc[mf][nf], ah[mf], bh[nf]);  // hi*hi
                    mma_bf16(acc[mf][nf], ah[mf], bl[nf]);  // hi*lo
                    mma_bf16(acc[mf][nf], al[mf], bh[nf]);  // lo*hi
                }
        }
        if (kt + 1 < nk) sstore(cur ^ 1);
        __syncthreads();
    }

    // epilogue with bias (m16n8 accumulator layout)
    #pragma unroll
    for (int mf = 0; mf < 2; mf++) {
        int row = bm + wm + mf*16 + g;
        #pragma unroll
        for (int nf = 0; nf < 4; nf++) {
            int col = bn + wn + nf*8 + (t << 1);
            float b0 = bias[col], b1 = bias[col+1];
            float2 v0 = make_float2(acc[mf][nf][0] + b0, acc[mf][nf][1] + b1);
            float2 v1 = make_float2(acc[mf][nf][2] + b0, acc[mf][nf][3] + b1);
            *reinterpret_cast<float2*>(C + (size_t)row*N + col)     = v0;
            *reinterpret_cast<float2*>(C + (size_t)(row+8)*N + col) = v1;
        }
    }
}

// ---------------- persistent GRU: weights in regs, packed f32x2 FMA -------------
// Hierarchical barrier: 8 leaf counters (16 CTAs each) -> root (8) -> gen word.
// Monotonic counters avoid reset races; contention per address is 16/8 not 128.
__device__ __forceinline__ void grid_sync()
{
    __threadfence();
    __syncthreads();
    if (threadIdx.x == 0) {
        unsigned gen = g_gen;
        if ((atomicAdd(&g_leaf[(blockIdx.x & 7) << 5], 1u) & 15u) == 15u) {
            if ((atomicAdd(&g_root, 1u) & 7u) == 7u) {
                __threadfence();
                g_gen = gen + 1;
            }
        }
        while (g_gen == gen) { }
    }
    __syncthreads();
}

__device__ __forceinline__ void fma2(unsigned long long& d,
                                     unsigned long long a,
                                     unsigned long long b)
{
    asm("fma.rn.f32x2 %0, %1, %2, %0;" : "+l"(d) : "l"(a), "l"(b));
}

__device__ __forceinline__ float hsum2(unsigned long long v)
{
    float x, y;
    asm("mov.b64 {%0,%1}, %2;" : "=f"(x), "=f"(y) : "l"(v));
    return x + y;
}

__device__ __forceinline__ float wsum(float v)
{
    v += __shfl_xor_sync(0xffffffffu, v, 16);
    v += __shfl_xor_sync(0xffffffffu, v, 8);
    v += __shfl_xor_sync(0xffffffffu, v, 4);
    v += __shfl_xor_sync(0xffffffffu, v, 2);
    v += __shfl_xor_sync(0xffffffffu, v, 1);
    return v;
}

__global__ void __launch_bounds__(256, 1)
gru_kernel(const float* __restrict__ xg,    // [MROWS, 3H], row = b*SEQ+s
           const float* __restrict__ whh,   // [3H, H]
           const float* __restrict__ bhh,   // [3H]
           const float* __restrict__ h0,    // [B, H]
           float* __restrict__ y,           // [B, SEQ, H]
           float* __restrict__ hA,
           float* __restrict__ hB)
{
    __shared__ float hs[BATCH*HID];         // 32KB

    const int tid = threadIdx.x;
    const int w   = tid >> 5;
    const int l   = tid & 31;
    const int j   = blockIdx.x * 8 + w;

    // persistent weight registers as f32x2 pairs
    ulonglong2 wr[8], wz[8], wn[8];
    #pragma unroll
    for (int i = 0; i < 8; i++) {
        int k = i*128 + (l << 2);
        wr[i] = *reinterpret_cast<const ulonglong2*>(whh + (size_t)(0*HID + j)*HID + k);
        wz[i] = *reinterpret_cast<const ulonglong2*>(whh + (size_t)(1*HID + j)*HID + k);
        wn[i] = *reinterpret_cast<const ulonglong2*>(whh + (size_t)(2*HID + j)*HID + k);
    }
    const float br  = bhh[j];
    const float bz  = bhh[HID + j];
    const float bn_ = bhh[2*HID + j];

    for (int s = 0; s < SEQ; s++) {
        const float* hsrc = (s == 0) ? h0 : ((s & 1) ? hA : hB);
        float*       hdst = (s & 1) ? hB : hA;

        // stage h into smem
        const float4* h4 = reinterpret_cast<const float4*>(hsrc);
        #pragma unroll
        for (int tt = 0; tt < 8; tt++) {
            int i = tid + tt*256;
            *reinterpret_cast<float4*>(&hs[i << 2]) = __ldcg(h4 + i);
        }
        __syncthreads();

        // prefetch pointwise inputs (lane l handles batch b=l)
        float xr = 0.f, xz = 0.f, xn = 0.f, hp = 0.f;
        if (l < 8) {
            size_t row = ((size_t)l*SEQ + s) * GATES;
            xr = __ldg(xg + row + j);
            xz = __ldg(xg + row + HID + j);
            xn = __ldg(xg + row + 2*HID + j);
            hp = hs[l*HID + j];
        }

        unsigned long long ar[8], az[8], an[8];
        #pragma unroll
        for (int b = 0; b < 8; b++) { ar[b] = 0ull; az[b] = 0ull; an[b] = 0ull; }
        #pragma unroll
        for (int b = 0; b < 8; b++) {
            const float* hb = hs + b*HID;
            #pragma unroll
            for (int i = 0; i < 8; i++) {
                ulonglong2 h2 = *reinterpret_cast<const ulonglong2*>(hb + i*128 + (l << 2));
                fma2(ar[b], h2.x, wr[i].x);
                fma2(ar[b], h2.y, wr[i].y);
                fma2(az[b], h2.x, wz[i].x);
                fma2(az[b], h2.y, wz[i].y);
                fma2(an[b], h2.x, wn[i].x);
                fma2(an[b], h2.y, wn[i].y);
            }
        }

        #pragma unroll
        for (int b = 0; b < 8; b++) {
            float R  = wsum(hsum2(ar[b]));
            float Z  = wsum(hsum2(az[b]));
            float Nn = wsum(hsum2(an[b]));
            if (l == b) {
                float r    = 1.f / (1.f + __expf(-(xr + R + br)));
                float z    = 1.f / (1.f + __expf(-(xz + Z + bz)));
                float n    = tanhf(xn + r * (Nn + bn_));
                float hnew = (1.f - z) * n + z * hp;
                hdst[b*HID + j] = hnew;
                y[((size_t)b*SEQ + s)*HID + j] = hnew;
            }
        }
        if (s + 1 < SEQ) grid_sync();
    }
}

// ---------------- launcher -----------------------------------------------------
extern "C" void kernel_launch(void* const* d_in, const int* in_sizes, int n_in,
                              void* d_out, int out_size)
{
    (void)in_sizes; (void)n_in; (void)out_size;
    const float* concepts  = (const float*)d_in[0];
    const int*   seq       = (const int*)  d_in[1];
    const float* embedding = (const float*)d_in[2];
    const float* w_ih      = (const float*)d_in[3];
    const float* w_hh      = (const float*)d_in[4];
    const float* b_ih      = (const float*)d_in[5];
    const float* b_hh      = (const float*)d_in[6];
    const float* fc_w      = (const float*)d_in[7];
    const float* fc_b      = (const float*)d_in[8];
    const float* c2h_w     = (const float*)d_in[9];
    const float* c2h_b     = (const float*)d_in[10];
    float* out = (float*)d_out;

    float *xg, *y0, *y1, *h0, *hA, *hB;
    cudaGetSymbolAddress((void**)&xg, g_xg);
    cudaGetSymbolAddress((void**)&y0, g_y0);
    cudaGetSymbolAddress((void**)&y1, g_y1);
    cudaGetSymbolAddress((void**)&h0, g_h0);
    cudaGetSymbolAddress((void**)&hA, g_hA);
    cudaGetSymbolAddress((void**)&hB, g_hB);

    cudaFuncSetAttribute(gemm_bf16x3<true>,  cudaFuncAttributeMaxDynamicSharedMemorySize, GSMEM);
    cudaFuncSetAttribute(gemm_bf16x3<false>, cudaFuncAttributeMaxDynamicSharedMemorySize, GSMEM);

    // 1) initial hidden states
    h0_kernel<<<BATCH, 256>>>(concepts, c2h_w, c2h_b);

    dim3 gx(MROWS/128, GATES/64);    // (32, 48)
    dim3 gl(MROWS/128, VOCAB/64);    // (32, 500)

    // 2) layer 0 input gates (embedding gather fused)
    gemm_bf16x3<true><<<gx, 256, GSMEM>>>(embedding, w_ih, b_ih, xg, seq,
                                          MROWS, GATES, HID);
    // 3) layer 0 recurrence
    gru_kernel<<<128, 256>>>(xg, w_hh, b_hh, h0, y0, hA, hB);
    // 4) layer 1 input gates
    gemm_bf16x3<false><<<gx, 256, GSMEM>>>(y0, w_ih + (size_t)GATES*HID,
                                           b_ih + GATES, xg, nullptr,
                                           MROWS, GATES, HID);
    // 5) layer 1 recurrence
    gru_kernel<<<128, 256>>>(xg, w_hh + (size_t)GATES*HID, b_hh + GATES,
                             h0 + BATCH*HID, y1, hA, hB);
    // 6) logits
    gemm_bf16x3<false><<<gl, 256, GSMEM>>>(y1, fc_w, fc_b, out, nullptr,
                                           MROWS, VOCAB, HID);
}

// round 10
// speedup vs baseline: 1.0588x; 1.0588x over previous
#include <cuda_runtime.h>
#include <cuda_bf16.h>
#include <math.h>

// Problem constants
#define HID    1024
#define VOCAB  32000
#define BATCH  8
#define SEQ    512
#define INDIM  768
#define MROWS  (BATCH*SEQ)      // 4096
#define GATES  (3*HID)          // 3072

// ---------------- scratch (no allocation allowed -> device globals) -----------
__device__ float g_h0init[2*BATCH*HID];      // [L][B][H]
__device__ float g_h0A[BATCH*HID];
__device__ float g_h0B[BATCH*HID];
__device__ float g_h1A[BATCH*HID];
__device__ float g_h1B[BATCH*HID];
__device__ float g_xg[(size_t)MROWS*GATES];  // layer-0 input gates
__device__ float g_y1[(size_t)MROWS*HID];    // layer-1 outputs (logits input)
__device__ unsigned int          g_barcnt = 0;
__device__ volatile unsigned int g_bargen = 0;

// ---------------- h0: global context + c2h projection --------------------------
__global__ void h0_kernel(const float* __restrict__ concepts,
                          const float* __restrict__ c2h_w,
                          const float* __restrict__ c2h_b)
{
    __shared__ float ctx[INDIM];
    int b = blockIdx.x, tid = threadIdx.x;
    for (int d = tid; d < INDIM; d += blockDim.x) {
        float s = 0.f;
        #pragma unroll
        for (int n = 0; n < 16; n++) s += concepts[(b*16 + n)*INDIM + d];
        ctx[d] = s * (1.0f/16.0f);
    }
    __syncthreads();
    for (int k = tid; k < 2*HID; k += blockDim.x) {
        const float* w = c2h_w + (size_t)k*INDIM;
        float acc = 0.f;
        #pragma unroll 4
        for (int d = 0; d < INDIM; d += 4) {
            acc += ctx[d+0]*w[d+0] + ctx[d+1]*w[d+1]
                 + ctx[d+2]*w[d+2] + ctx[d+3]*w[d+3];
        }
        acc += c2h_b[k];
        int l = k >> 10, j = k & (HID-1);
        g_h0init[(l*BATCH + b)*HID + j] = acc;
    }
}

// ---------------- bf16x3 tensor-core GEMM, 2 CTAs/SM ---------------------------
#define GLDW  20
#define GTA   (128*GLDW)
#define GTB   (64*GLDW)
#define GBUF  (2*GTA + 2*GTB)
#define GSMEM (2*GBUF*4)

__device__ __forceinline__ unsigned pack_bf2(float a, float b)
{
    __nv_bfloat162 t = __floats2bfloat162_rn(a, b);
    return *reinterpret_cast<unsigned*>(&t);
}

__device__ __forceinline__ void split_pair(float x, float y,
                                           unsigned& hi, unsigned& lo)
{
    hi = pack_bf2(x, y);
    __nv_bfloat162 hh = *reinterpret_cast<__nv_bfloat162*>(&hi);
    lo = pack_bf2(x - __bfloat162float(hh.x), y - __bfloat162float(hh.y));
}

__device__ __forceinline__ void mma_bf16(float* d, const unsigned* a, const unsigned* b)
{
    asm volatile(
        "mma.sync.aligned.m16n8k16.row.col.f32.bf16.bf16.f32 "
        "{%0,%1,%2,%3},{%4,%5,%6,%7},{%8,%9},{%0,%1,%2,%3};"
        : "+f"(d[0]), "+f"(d[1]), "+f"(d[2]), "+f"(d[3])
        : "r"(a[0]), "r"(a[1]), "r"(a[2]), "r"(a[3]), "r"(b[0]), "r"(b[1]));
}

template<bool GATHER>
__global__ void __launch_bounds__(256, 2)
gemm_bf16x3(const float* __restrict__ A, const float* __restrict__ B,
            const float* __restrict__ bias, float* __restrict__ C,
            const int* __restrict__ gidx, int M, int N, int K)
{
    extern __shared__ unsigned sm[];
    const int tid = threadIdx.x;
    const int l   = tid & 31;
    const int wid = tid >> 5;
    const int wm  = (wid & 3) * 32;
    const int wn  = (wid >> 2) * 32;
    const int bm  = blockIdx.x * 128;
    const int bn  = blockIdx.y * 64;
    const int g   = l >> 2;
    const int t   = l & 3;

    int aploc[4], bploc[2];
    const float* aptr[4];
    const float* bptr[2];
    #pragma unroll
    for (int u = 0; u < 4; u++) {
        int f    = tid + u*256;
        int row  = f >> 3;
        int kf   = (f & 7) << 2;
        aploc[u] = row*GLDW + ((f & 7) << 1);
        int ar   = GATHER ? gidx[bm + row] : (bm + row);
        aptr[u]  = A + (size_t)ar*K + kf;
    }
    #pragma unroll
    for (int u = 0; u < 2; u++) {
        int f    = tid + u*256;
        int row  = f >> 3;
        int kf   = (f & 7) << 2;
        bploc[u] = row*GLDW + ((f & 7) << 1);
        bptr[u]  = B + (size_t)(bn + row)*K + kf;
    }

    float acc[2][4][4];
    #pragma unroll
    for (int i = 0; i < 2; i++)
        #pragma unroll
        for (int jj = 0; jj < 4; jj++)
            #pragma unroll
            for (int r = 0; r < 4; r++) acc[i][jj][r] = 0.f;

    float4 va[4], vb[2];
    auto gload = [&](int kt) {
        #pragma unroll
        for (int u = 0; u < 4; u++)
            va[u] = *reinterpret_cast<const float4*>(aptr[u] + kt*32);
        #pragma unroll
        for (int u = 0; u < 2; u++)
            vb[u] = *reinterpret_cast<const float4*>(bptr[u] + kt*32);
    };
    auto sstore = [&](int buf) {
        unsigned* Ah = sm + buf*GBUF;
        unsigned* Al = Ah + GTA;
        unsigned* Bh = Al + GTA;
        unsigned* Bl = Bh + GTB;
        #pragma unroll
        for (int u = 0; u < 4; u++) {
            unsigned h0, l0, h1, l1;
            split_pair(va[u].x, va[u].y, h0, l0);
            split_pair(va[u].z, va[u].w, h1, l1);
            Ah[aploc[u]] = h0; Ah[aploc[u]+1] = h1;
            Al[aploc[u]] = l0; Al[aploc[u]+1] = l1;
        }
        #pragma unroll
        for (int u = 0; u < 2; u++) {
            unsigned h0, l0, h1, l1;
            split_pair(vb[u].x, vb[u].y, h0, l0);
            split_pair(vb[u].z, vb[u].w, h1, l1);
            Bh[bploc[u]] = h0; Bh[bploc[u]+1] = h1;
            Bl[bploc[u]] = l0; Bl[bploc[u]+1] = l1;
        }
    };

    const int nk = K / 32;
    gload(0); sstore(0); __syncthreads();

    for (int kt = 0; kt < nk; kt++) {
        int cur = kt & 1;
        if (kt + 1 < nk) gload(kt + 1);

        const unsigned* Ah = sm + cur*GBUF;
        const unsigned* Al = Ah + GTA;
        const unsigned* Bh = Al + GTA;
        const unsigned* Bl = Bh + GTB;

        #pragma unroll
        for (int kh = 0; kh < 2; kh++) {
            const int bp = kh * 8;
            unsigned ah[2][4], al[2][4], bh[4][2], bl[4][2];
            #pragma unroll
            for (int mf = 0; mf < 2; mf++) {
                int r0 = (wm + mf*16 + g)*GLDW + bp + t;
                ah[mf][0] = Ah[r0];
                ah[mf][1] = Ah[r0 + 8*GLDW];
                ah[mf][2] = Ah[r0 + 4];
                ah[mf][3] = Ah[r0 + 8*GLDW + 4];
                al[mf][0] = Al[r0];
                al[mf][1] = Al[r0 + 8*GLDW];
                al[mf][2] = Al[r0 + 4];
                al[mf][3] = Al[r0 + 8*GLDW + 4];
            }
            #pragma unroll
            for (int nf = 0; nf < 4; nf++) {
                int c0 = (wn + nf*8 + g)*GLDW + bp + t;
                bh[nf][0] = Bh[c0];
                bh[nf][1] = Bh[c0 + 4];
                bl[nf][0] = Bl[c0];
                bl[nf][1] = Bl[c0 + 4];
            }
            #pragma unroll
            for (int mf = 0; mf < 2; mf++)
                #pragma unroll
                for (int nf = 0; nf < 4; nf++) {
                    mma_bf16(acc[mf][nf], ah[mf], bh[nf]);
                    mma_bf16(acc[mf][nf], ah[mf], bl[nf]);
                    mma_bf16(acc[mf][nf], al[mf], bh[nf]);
                }
        }
        if (kt + 1 < nk) sstore(cur ^ 1);
        __syncthreads();
    }

    #pragma unroll
    for (int mf = 0; mf < 2; mf++) {
        int row = bm + wm + mf*16 + g;
        #pragma unroll
        for (int nf = 0; nf < 4; nf++) {
            int col = bn + wn + nf*8 + (t << 1);
            float b0 = bias[col], b1 = bias[col+1];
            float2 v0 = make_float2(acc[mf][nf][0] + b0, acc[mf][nf][1] + b1);
            float2 v1 = make_float2(acc[mf][nf][2] + b0, acc[mf][nf][3] + b1);
            *reinterpret_cast<float2*>(C + (size_t)row*N + col)     = v0;
            *reinterpret_cast<float2*>(C + (size_t)(row+8)*N + col) = v1;
        }
    }
}

// ---------------- fused two-layer pipelined GRU --------------------------------
// Round r: layer0 step r (r<512) + layer1 step r-1 (r>=1). 513 rounds, 512 grid
// barriers (vs 1022 split). Layer1's input y0[r-1] IS the hs0 staged this round.
// Single-atomic barrier (R5/R7 proven) + nanosleep backoff in the spin.
__device__ __forceinline__ void grid_sync()
{
    __threadfence();
    __syncthreads();
    if (threadIdx.x == 0) {
        unsigned int gen = g_bargen;
        if (atomicAdd(&g_barcnt, 1) == gridDim.x - 1) {
            g_barcnt = 0;
            __threadfence();
            g_bargen = gen + 1;
        } else {
            while (g_bargen == gen) { __nanosleep(64); }
        }
    }
    __syncthreads();
}

__device__ __forceinline__ void fma2(unsigned long long& d,
                                     unsigned long long a,
                                     unsigned long long b)
{
    asm("fma.rn.f32x2 %0, %1, %2, %0;" : "+l"(d) : "l"(a), "l"(b));
}

__device__ __forceinline__ float hsum2(unsigned long long v)
{
    float x, y;
    asm("mov.b64 {%0,%1}, %2;" : "=f"(x), "=f"(y) : "l"(v));
    return x + y;
}

__device__ __forceinline__ float wsum(float v)
{
    v += __shfl_xor_sync(0xffffffffu, v, 16);
    v += __shfl_xor_sync(0xffffffffu, v, 8);
    v += __shfl_xor_sync(0xffffffffu, v, 4);
    v += __shfl_xor_sync(0xffffffffu, v, 2);
    v += __shfl_xor_sync(0xffffffffu, v, 1);
    return v;
}

// dynamic smem: hs0(8192) + hs1(8192) + L1 hh weights(24576) floats = 163840 B
#define FUSED_SMEM ((8192 + 8192 + 24576) * 4)

__global__ void __launch_bounds__(256, 1)
gru_fused(const float* __restrict__ xg,     // [B*SEQ, 3H] layer-0 input gates
          const float* __restrict__ whh0,
          const float* __restrict__ bhh0,
          const float* __restrict__ wih1,
          const float* __restrict__ bih1,
          const float* __restrict__ whh1,
          const float* __restrict__ bhh1,
          const float* __restrict__ h0i,    // layer-0 init state [B,H]
          const float* __restrict__ h1i,    // layer-1 init state [B,H]
          float* __restrict__ y1,           // [B,SEQ,H]
          float* h0A, float* h0B, float* h1A, float* h1B)
{
    extern __shared__ float smf[];
    float* hs0 = smf;                 // 32KB: y0[r-1] == h0 state pre-step-r
    float* hs1 = smf + 8192;          // 32KB: h1 state pre-step
    float* wsm = smf + 16384;         // 96KB: L1 hh weights

    const int tid  = threadIdx.x;
    const int w    = tid >> 5;
    const int l    = tid & 31;
    const int j    = blockIdx.x * 8 + w;
    const int koff = l << 2;

    // persistent L0 hh weights (96 regs)
    ulonglong2 wr0[8], wz0[8], wn0[8];
    #pragma unroll
    for (int i = 0; i < 8; i++) {
        int k = i*128 + koff;
        wr0[i] = *reinterpret_cast<const ulonglong2*>(whh0 + (size_t)(0*HID + j)*HID + k);
        wz0[i] = *reinterpret_cast<const ulonglong2*>(whh0 + (size_t)(1*HID + j)*HID + k);
        wn0[i] = *reinterpret_cast<const ulonglong2*>(whh0 + (size_t)(2*HID + j)*HID + k);
    }
    // L1 hh weights -> smem (once). layout ((w*3+g)*8+i)*128 + koff
    #pragma unroll
    for (int g = 0; g < 3; g++)
        #pragma unroll
        for (int i = 0; i < 8; i++) {
            float4 v = *reinterpret_cast<const float4*>(
                whh1 + (size_t)(g*HID + j)*HID + i*128 + koff);
            *reinterpret_cast<float4*>(wsm + (((w*3 + g)*8 + i) << 7) + koff) = v;
        }

    const float br0 = bhh0[j], bz0 = bhh0[HID + j], bn0 = bhh0[2*HID + j];
    const float bA1 = bih1[j] + bhh1[j];
    const float bB1 = bih1[HID + j] + bhh1[HID + j];
    const float bC1 = bih1[2*HID + j];
    const float bD1 = bhh1[2*HID + j];

    // prefetch xg for step 0 (lane l handles batch b=l)
    float pxr = 0.f, pxz = 0.f, pxn = 0.f;
    if (l < 8) {
        size_t row = ((size_t)l*SEQ + 0) * GATES;
        pxr = __ldg(xg + row + j);
        pxz = __ldg(xg + row + HID + j);
        pxn = __ldg(xg + row + 2*HID + j);
    }

    for (int r = 0; r <= SEQ; r++) {
        const int s1 = r - 1;

        // stage h-states into smem
        {
            const float* src0 = (r == 0) ? h0i : ((r & 1) ? h0A : h0B);
            const float4* p0 = reinterpret_cast<const float4*>(src0);
            #pragma unroll
            for (int t = 0; t < 8; t++) {
                int i = tid + t*256;
                *reinterpret_cast<float4*>(&hs0[i << 2]) = __ldcg(p0 + i);
            }
            if (r >= 1) {
                const float* src1 = (s1 == 0) ? h1i : ((s1 & 1) ? h1A : h1B);
                const float4* p1 = reinterpret_cast<const float4*>(src1);
                #pragma unroll
                for (int t = 0; t < 8; t++) {
                    int i = tid + t*256;
                    *reinterpret_cast<float4*>(&hs1[i << 2]) = __ldcg(p1 + i);
                }
            }
        }
        __syncthreads();

        // ---- layer 0, step r ----
        if (r < SEQ) {
            float* dst0 = (r & 1) ? h0B : h0A;
            float hp0 = (l < 8) ? hs0[l*HID + j] : 0.f;

            unsigned long long ar[8], az[8], an[8];
            #pragma unroll
            for (int b = 0; b < 8; b++) { ar[b] = 0ull; az[b] = 0ull; an[b] = 0ull; }
            #pragma unroll
            for (int b = 0; b < 8; b++) {
                const float* hb = hs0 + b*HID;
                #pragma unroll
                for (int i = 0; i < 8; i++) {
                    ulonglong2 h2 = *reinterpret_cast<const ulonglong2*>(hb + i*128 + koff);
                    fma2(ar[b], h2.x, wr0[i].x);
                    fma2(ar[b], h2.y, wr0[i].y);
                    fma2(az[b], h2.x, wz0[i].x);
                    fma2(az[b], h2.y, wz0[i].y);
                    fma2(an[b], h2.x, wn0[i].x);
                    fma2(an[b], h2.y, wn0[i].y);
                }
            }
            #pragma unroll
            for (int b = 0; b < 8; b++) {
                float R  = wsum(hsum2(ar[b]));
                float Z  = wsum(hsum2(az[b]));
                float Nn = wsum(hsum2(an[b]));
                if (l == b) {
                    float rg   = 1.f / (1.f + __expf(-(pxr + R + br0)));
                    float zg   = 1.f / (1.f + __expf(-(pxz + Z + bz0)));
                    float ng   = tanhf(pxn + rg * (Nn + bn0));
                    float hnew = (1.f - zg) * ng + zg * hp0;
                    dst0[b*HID + j] = hnew;
                }
            }
        }

        // ---- layer 1, step r-1 (input = hs0 staged this round) ----
        if (r >= 1) {
            float* dst1 = (s1 & 1) ? h1B : h1A;
            float hp1 = (l < 8) ? hs1[l*HID + j] : 0.f;

            unsigned long long A[8], Bc[8], Cc[8], Dc[8];
            #pragma unroll
            for (int b = 0; b < 8; b++) { A[b]=0ull; Bc[b]=0ull; Cc[b]=0ull; Dc[b]=0ull; }

            const float* wsw = wsm + ((w*3) << 10);   // this warp's 3 gate rows
            #pragma unroll 2
            for (int i = 0; i < 8; i++) {
                int k = i*128 + koff;
                ulonglong2 ur = *reinterpret_cast<const ulonglong2*>(wih1 + (size_t)(0*HID + j)*HID + k);
                ulonglong2 uz = *reinterpret_cast<const ulonglong2*>(wih1 + (size_t)(1*HID + j)*HID + k);
                ulonglong2 un = *reinterpret_cast<const ulonglong2*>(wih1 + (size_t)(2*HID + j)*HID + k);
                ulonglong2 vr = *reinterpret_cast<const ulonglong2*>(wsw + (0*8 + i)*128 + koff);
                ulonglong2 vz = *reinterpret_cast<const ulonglong2*>(wsw + (1*8 + i)*128 + koff);
                ulonglong2 vn = *reinterpret_cast<const ulonglong2*>(wsw + (2*8 + i)*128 + koff);
                #pragma unroll
                for (int b = 0; b < 8; b++) {
                    ulonglong2 yv = *reinterpret_cast<const ulonglong2*>(hs0 + b*HID + i*128 + koff);
                    ulonglong2 hv = *reinterpret_cast<const ulonglong2*>(hs1 + b*HID + i*128 + koff);
                    fma2(A[b],  yv.x, ur.x); fma2(A[b],  yv.y, ur.y);
                    fma2(A[b],  hv.x, vr.x); fma2(A[b],  hv.y, vr.y);
                    fma2(Bc[b], yv.x, uz.x); fma2(Bc[b], yv.y, uz.y);
                    fma2(Bc[b], hv.x, vz.x); fma2(Bc[b], hv.y, vz.y);
                    fma2(Cc[b], yv.x, un.x); fma2(Cc[b], yv.y, un.y);
                    fma2(Dc[b], hv.x, vn.x); fma2(Dc[b], hv.y, vn.y);
                }
            }
            #pragma unroll
            for (int b = 0; b < 8; b++) {
                float Av = wsum(hsum2(A[b]));
                float Bv = wsum(hsum2(Bc[b]));
                float Cv = wsum(hsum2(Cc[b]));
                float Dv = wsum(hsum2(Dc[b]));
                if (l == b) {
                    float rg   = 1.f / (1.f + __expf(-(Av + bA1)));
                    float zg   = 1.f / (1.f + __expf(-(Bv + bB1)));
                    float ng   = tanhf(Cv + bC1 + rg * (Dv + bD1));
                    float hnew = (1.f - zg) * ng + zg * hp1;
                    dst1[b*HID + j] = hnew;
                    y1[((size_t)b*SEQ + s1)*HID + j] = hnew;
                }
            }
        }

        // prefetch next round's layer-0 gates (off critical path)
        if (l < 8 && r + 1 < SEQ) {
            size_t row = ((size_t)l*SEQ + (r + 1)) * GATES;
            pxr = __ldg(xg + row + j);
            pxz = __ldg(xg + row + HID + j);
            pxn = __ldg(xg + row + 2*HID + j);
        }

        if (r < SEQ) grid_sync();
    }
}

// ---------------- launcher -----------------------------------------------------
extern "C" void kernel_launch(void* const* d_in, const int* in_sizes, int n_in,
                              void* d_out, int out_size)
{
    (void)in_sizes; (void)n_in; (void)out_size;
    const float* concepts  = (const float*)d_in[0];
    const int*   seq       = (const int*)  d_in[1];
    const float* embedding = (const float*)d_in[2];
    const float* w_ih      = (const float*)d_in[3];
    const float* w_hh      = (const float*)d_in[4];
    const float* b_ih      = (const float*)d_in[5];
    const float* b_hh      = (const float*)d_in[6];
    const float* fc_w      = (const float*)d_in[7];
    const float* fc_b      = (const float*)d_in[8];
    const float* c2h_w     = (const float*)d_in[9];
    const float* c2h_b     = (const float*)d_in[10];
    float* out = (float*)d_out;

    float *xg, *y1, *h0i, *h0A, *h0B, *h1A, *h1B;
    cudaGetSymbolAddress((void**)&xg,  g_xg);
    cudaGetSymbolAddress((void**)&y1,  g_y1);
    cudaGetSymbolAddress((void**)&h0i, g_h0init);
    cudaGetSymbolAddress((void**)&h0A, g_h0A);
    cudaGetSymbolAddress((void**)&h0B, g_h0B);
    cudaGetSymbolAddress((void**)&h1A, g_h1A);
    cudaGetSymbolAddress((void**)&h1B, g_h1B);

    cudaFuncSetAttribute(gemm_bf16x3<true>,  cudaFuncAttributeMaxDynamicSharedMemorySize, GSMEM);
    cudaFuncSetAttribute(gemm_bf16x3<false>, cudaFuncAttributeMaxDynamicSharedMemorySize, GSMEM);
    cudaFuncSetAttribute(gru_fused, cudaFuncAttributeMaxDynamicSharedMemorySize, FUSED_SMEM);

    // 1) initial hidden states
    h0_kernel<<<BATCH, 256>>>(concepts, c2h_w, c2h_b);

    dim3 gx(MROWS/128, GATES/64);    // (32, 48)
    dim3 gl(MROWS/128, VOCAB/64);    // (32, 500)

    // 2) layer-0 input gates (embedding gather fused)
    gemm_bf16x3<true><<<gx, 256, GSMEM>>>(embedding, w_ih, b_ih, xg, seq,
                                          MROWS, GATES, HID);
    // 3) fused two-layer recurrence (replaces gru x2 + xg1 GEMM)
    gru_fused<<<128, 256, FUSED_SMEM>>>(
        xg,
        w_hh, b_hh,
        w_ih + (size_t)GATES*HID, b_ih + GATES,
        w_hh + (size_t)GATES*HID, b_hh + GATES,
        h0i, h0i + BATCH*HID,
        y1, h0A, h0B, h1A, h1B);
    // 4) logits
    gemm_bf16x3<false><<<gl, 256, GSMEM>>>(y1, fc_w, fc_b, out, nullptr,
                                           MROWS, VOCAB, HID);
}

// round 12
// speedup vs baseline: 1.0791x; 1.0192x over previous
#include <cuda_runtime.h>
#include <cuda_bf16.h>
#include <math.h>

// Problem constants
#define HID    1024
#define VOCAB  32000
#define BATCH  8
#define SEQ    512
#define INDIM  768
#define MROWS  (BATCH*SEQ)      // 4096
#define GATES  (3*HID)          // 3072

// ---------------- scratch (no allocation allowed -> device globals) -----------
__device__ float g_h0init[2*BATCH*HID];      // [L][B][H]
__device__ float g_h0A[BATCH*HID];
__device__ float g_h0B[BATCH*HID];
__device__ float g_h1A[BATCH*HID];
__device__ float g_h1B[BATCH*HID];
__device__ float g_xg[(size_t)MROWS*GATES];  // layer-0 input gates
__device__ float g_y1[(size_t)MROWS*HID];    // layer-1 outputs (logits input)
__device__ unsigned int          g_barcnt = 0;
__device__ volatile unsigned int g_bargen = 0;

// ---------------- h0: global context + c2h projection --------------------------
__global__ void h0_kernel(const float* __restrict__ concepts,
                          const float* __restrict__ c2h_w,
                          const float* __restrict__ c2h_b)
{
    __shared__ float ctx[INDIM];
    int b = blockIdx.x, tid = threadIdx.x;
    for (int d = tid; d < INDIM; d += blockDim.x) {
        float s = 0.f;
        #pragma unroll
        for (int n = 0; n < 16; n++) s += concepts[(b*16 + n)*INDIM + d];
        ctx[d] = s * (1.0f/16.0f);
    }
    __syncthreads();
    for (int k = tid; k < 2*HID; k += blockDim.x) {
        const float* w = c2h_w + (size_t)k*INDIM;
        float acc = 0.f;
        #pragma unroll 4
        for (int d = 0; d < INDIM; d += 4) {
            acc += ctx[d+0]*w[d+0] + ctx[d+1]*w[d+1]
                 + ctx[d+2]*w[d+2] + ctx[d+3]*w[d+3];
        }
        acc += c2h_b[k];
        int l = k >> 10, j = k & (HID-1);
        g_h0init[(l*BATCH + b)*HID + j] = acc;
    }
}

// ---------------- bf16x3 tensor-core GEMM, 2 CTAs/SM, ldmatrix -----------------
// C[M,N] = A[M,K] * B[N,K]^T + bias[N]. Tile 128(M)x64(N), BK=32, 256 threads
// (8 warps, 4m x 2n, warp 32x32), mma.m16n8k16 with ldmatrix fragment loads.
#define GLDW  20                 // b32 words per row (16 data + 4 pad)
#define GTA   (128*GLDW)         // A tile words (2560)
#define GTB   (64*GLDW)          // B tile words (1280)
#define GBUF  (2*GTA + 2*GTB)    // words per buffer {Ah,Al,Bh,Bl} = 7680
#define GSMEM (2*GBUF*4)         // 61440 bytes

__device__ __forceinline__ unsigned pack_bf2(float a, float b)
{
    __nv_bfloat162 t = __floats2bfloat162_rn(a, b);
    return *reinterpret_cast<unsigned*>(&t);
}

__device__ __forceinline__ void split_pair(float x, float y,
                                           unsigned& hi, unsigned& lo)
{
    hi = pack_bf2(x, y);
    __nv_bfloat162 hh = *reinterpret_cast<__nv_bfloat162*>(&hi);
    lo = pack_bf2(x - __bfloat162float(hh.x), y - __bfloat162float(hh.y));
}

__device__ __forceinline__ void mma_bf16(float* d, const unsigned* a, const unsigned* b)
{
    asm volatile(
        "mma.sync.aligned.m16n8k16.row.col.f32.bf16.bf16.f32 "
        "{%0,%1,%2,%3},{%4,%5,%6,%7},{%8,%9},{%0,%1,%2,%3};"
        : "+f"(d[0]), "+f"(d[1]), "+f"(d[2]), "+f"(d[3])
        : "r"(a[0]), "r"(a[1]), "r"(a[2]), "r"(a[3]), "r"(b[0]), "r"(b[1]));
}

__device__ __forceinline__ void ldsm_x4(unsigned* r, unsigned addr)
{
    asm volatile(
        "ldmatrix.sync.aligned.m8n8.x4.shared.b16 {%0,%1,%2,%3}, [%4];"
        : "=r"(r[0]), "=r"(r[1]), "=r"(r[2]), "=r"(r[3]) : "r"(addr));
}

template<bool GATHER>
__global__ void __launch_bounds__(256, 2)
gemm_bf16x3(const float* __restrict__ A, const float* __restrict__ B,
            const float* __restrict__ bias, float* __restrict__ C,
            const int* __restrict__ gidx, int M, int N, int K)
{
    extern __shared__ unsigned sm[];
    const unsigned smb = (unsigned)__cvta_generic_to_shared(sm);
    const int tid = threadIdx.x;
    const int l   = tid & 31;
    const int wid = tid >> 5;
    const int wm  = (wid & 3) * 32;
    const int wn  = (wid >> 2) * 32;
    const int bm  = blockIdx.x * 128;
    const int bn  = blockIdx.y * 64;
    const int g   = l >> 2;
    const int t   = l & 3;
    // ldmatrix lane decomposition: tile = l>>3, row-in-tile = l&7
    const int lr  = l & 7;
    const int qA  = (l >> 3) & 1;   // +8 rows for odd tiles (A)
    const int qW  = (l >> 4);       // +4 words for tiles 2,3 (A) / nf select (B)

    int aploc[4], bploc[2];
    const float* aptr[4];
    const float* bptr[2];
    #pragma unroll
    for (int u = 0; u < 4; u++) {
        int f    = tid + u*256;
        int row  = f >> 3;
        int kf   = (f & 7) << 2;
        aploc[u] = row*GLDW + ((f & 7) << 1);
        int ar   = GATHER ? gidx[bm + row] : (bm + row);
        aptr[u]  = A + (size_t)ar*K + kf;
    }
    #pragma unroll
    for (int u = 0; u < 2; u++) {
        int f    = tid + u*256;
        int row  = f >> 3;
        int kf   = (f & 7) << 2;
        bploc[u] = row*GLDW + ((f & 7) << 1);
        bptr[u]  = B + (size_t)(bn + row)*K + kf;
    }

    float acc[2][4][4];
    #pragma unroll
    for (int i = 0; i < 2; i++)
        #pragma unroll
        for (int jj = 0; jj < 4; jj++)
            #pragma unroll
            for (int r = 0; r < 4; r++) acc[i][jj][r] = 0.f;

    float4 va[4], vb[2];
    auto gload = [&](int kt) {
        #pragma unroll
        for (int u = 0; u < 4; u++)
            va[u] = *reinterpret_cast<const float4*>(aptr[u] + kt*32);
        #pragma unroll
        for (int u = 0; u < 2; u++)
            vb[u] = *reinterpret_cast<const float4*>(bptr[u] + kt*32);
    };
    auto sstore = [&](int buf) {
        unsigned* Ah = sm + buf*GBUF;
        unsigned* Al = Ah + GTA;
        unsigned* Bh = Al + GTA;
        unsigned* Bl = Bh + GTB;
        #pragma unroll
        for (int u = 0; u < 4; u++) {
            unsigned h0, l0, h1, l1;
            split_pair(va[u].x, va[u].y, h0, l0);
            split_pair(va[u].z, va[u].w, h1, l1);
            Ah[aploc[u]] = h0; Ah[aploc[u]+1] = h1;
            Al[aploc[u]] = l0; Al[aploc[u]+1] = l1;
        }
        #pragma unroll
        for (int u = 0; u < 2; u++) {
            unsigned h0, l0, h1, l1;
            split_pair(vb[u].x, vb[u].y, h0, l0);
            split_pair(vb[u].z, vb[u].w, h1, l1);
            Bh[bploc[u]] = h0; Bh[bploc[u]+1] = h1;
            Bl[bploc[u]] = l0; Bl[bploc[u]+1] = l1;
        }
    };

    const int nk = K / 32;
    gload(0); sstore(0); __syncthreads();

    for (int kt = 0; kt < nk; kt++) {
        int cur = kt & 1;
        if (kt + 1 < nk) gload(kt + 1);

        const unsigned AhB = smb + (cur*GBUF)*4u;
        const unsigned AlB = AhB + GTA*4u;
        const unsigned BhB = AlB + GTA*4u;
        const unsigned BlB = BhB + GTB*4u;

        #pragma unroll
        for (int kh = 0; kh < 2; kh++) {
            const int bp = kh * 8;
            unsigned ah[2][4], al[2][4], bh[4][2], bl[4][2];
            // A fragments: tiles = {rows, bp} {rows+8, bp} {rows, bp+4} {rows+8, bp+4}
            #pragma unroll
            for (int mf = 0; mf < 2; mf++) {
                unsigned aoff = (unsigned)((wm + mf*16 + qA*8 + lr)*GLDW
                                           + bp + (qW << 2)) * 4u;
                ldsm_x4(ah[mf], AhB + aoff);
                ldsm_x4(al[mf], AlB + aoff);
            }
            // B fragments: x4 covers nf pair (2p, 2p+1)
            #pragma unroll
            for (int p = 0; p < 2; p++) {
                unsigned boff = (unsigned)((wn + (p*2 + qW)*8 + lr)*GLDW
                                           + bp + (((l >> 3) & 1) << 2)) * 4u;
                unsigned tmp[4];
                ldsm_x4(tmp, BhB + boff);
                bh[2*p][0] = tmp[0]; bh[2*p][1] = tmp[1];
                bh[2*p+1][0] = tmp[2]; bh[2*p+1][1] = tmp[3];
                ldsm_x4(tmp, BlB + boff);
                bl[2*p][0] = tmp[0]; bl[2*p][1] = tmp[1];
                bl[2*p+1][0] = tmp[2]; bl[2*p+1][1] = tmp[3];
            }
            #pragma unroll
            for (int mf = 0; mf < 2; mf++)
                #pragma unroll
                for (int nf = 0; nf < 4; nf++) {
                    mma_bf16(acc[mf][nf], ah[mf], bh[nf]);
                    mma_bf16(acc[mf][nf], ah[mf], bl[nf]);
                    mma_bf16(acc[mf][nf], al[mf], bh[nf]);
                }
        }
        if (kt + 1 < nk) sstore(cur ^ 1);
        __syncthreads();
    }

    #pragma unroll
    for (int mf = 0; mf < 2; mf++) {
        int row = bm + wm + mf*16 + g;
        #pragma unroll
        for (int nf = 0; nf < 4; nf++) {
            int col = bn + wn + nf*8 + (t << 1);
            float b0 = bias[col], b1 = bias[col+1];
            float2 v0 = make_float2(acc[mf][nf][0] + b0, acc[mf][nf][1] + b1);
            float2 v1 = make_float2(acc[mf][nf][2] + b0, acc[mf][nf][3] + b1);
            *reinterpret_cast<float2*>(C + (size_t)row*N + col)     = v0;
            *reinterpret_cast<float2*>(C + (size_t)(row+8)*N + col) = v1;
        }
    }
}

// ---------------- fused two-layer pipelined GRU (R10 passing version) ----------
__device__ __forceinline__ void grid_sync()
{
    __threadfence();
    __syncthreads();
    if (threadIdx.x == 0) {
        unsigned int gen = g_bargen;
        if (atomicAdd(&g_barcnt, 1) == gridDim.x - 1) {
            g_barcnt = 0;
            __threadfence();
            g_bargen = gen + 1;
        } else {
            while (g_bargen == gen) { __nanosleep(64); }
        }
    }
    __syncthreads();
}

__device__ __forceinline__ void fma2(unsigned long long& d,
                                     unsigned long long a,
                                     unsigned long long b)
{
    asm("fma.rn.f32x2 %0, %1, %2, %0;" : "+l"(d) : "l"(a), "l"(b));
}

__device__ __forceinline__ float hsum2(unsigned long long v)
{
    float x, y;
    asm("mov.b64 {%0,%1}, %2;" : "=f"(x), "=f"(y) : "l"(v));
    return x + y;
}

__device__ __forceinline__ float wsum(float v)
{
    v += __shfl_xor_sync(0xffffffffu, v, 16);
    v += __shfl_xor_sync(0xffffffffu, v, 8);
    v += __shfl_xor_sync(0xffffffffu, v, 4);
    v += __shfl_xor_sync(0xffffffffu, v, 2);
    v += __shfl_xor_sync(0xffffffffu, v, 1);
    return v;
}

#define FUSED_SMEM ((8192 + 8192 + 24576) * 4)

__global__ void __launch_bounds__(256, 1)
gru_fused(const float* __restrict__ xg,
          const float* __restrict__ whh0,
          const float* __restrict__ bhh0,
          const float* __restrict__ wih1,
          const float* __restrict__ bih1,
          const float* __restrict__ whh1,
          const float* __restrict__ bhh1,
          const float* __restrict__ h0i,
          const float* __restrict__ h1i,
          float* __restrict__ y1,
          float* h0A, float* h0B, float* h1A, float* h1B)
{
    extern __shared__ float smf[];
    float* hs0 = smf;
    float* hs1 = smf + 8192;
    float* wsm = smf + 16384;

    const int tid  = threadIdx.x;
    const int w    = tid >> 5;
    const int l    = tid & 31;
    const int j    = blockIdx.x * 8 + w;
    const int koff = l << 2;

    ulonglong2 wr0[8], wz0[8], wn0[8];
    #pragma unroll
    for (int i = 0; i < 8; i++) {
        int k = i*128 + koff;
        wr0[i] = *reinterpret_cast<const ulonglong2*>(whh0 + (size_t)(0*HID + j)*HID + k);
        wz0[i] = *reinterpret_cast<const ulonglong2*>(whh0 + (size_t)(1*HID + j)*HID + k);
        wn0[i] = *reinterpret_cast<const ulonglong2*>(whh0 + (size_t)(2*HID + j)*HID + k);
    }
    #pragma unroll
    for (int g = 0; g < 3; g++)
        #pragma unroll
        for (int i = 0; i < 8; i++) {
            float4 v = *reinterpret_cast<const float4*>(
                whh1 + (size_t)(g*HID + j)*HID + i*128 + koff);
            *reinterpret_cast<float4*>(wsm + (((w*3 + g)*8 + i) << 7) + koff) = v;
        }

    const float br0 = bhh0[j], bz0 = bhh0[HID + j], bn0 = bhh0[2*HID + j];
    const float bA1 = bih1[j] + bhh1[j];
    const float bB1 = bih1[HID + j] + bhh1[HID + j];
    const float bC1 = bih1[2*HID + j];
    const float bD1 = bhh1[2*HID + j];

    float pxr = 0.f, pxz = 0.f, pxn = 0.f;
    if (l < 8) {
        size_t row = ((size_t)l*SEQ + 0) * GATES;
        pxr = __ldg(xg + row + j);
        pxz = __ldg(xg + row + HID + j);
        pxn = __ldg(xg + row + 2*HID + j);
    }

    for (int r = 0; r <= SEQ; r++) {
        const int s1 = r - 1;

        {
            const float* src0 = (r == 0) ? h0i : ((r & 1) ? h0A : h0B);
            const float4* p0 = reinterpret_cast<const float4*>(src0);
            #pragma unroll
            for (int t = 0; t < 8; t++) {
                int i = tid + t*256;
                *reinterpret_cast<float4*>(&hs0[i << 2]) = __ldcg(p0 + i);
            }
            if (r >= 1) {
                const float* src1 = (s1 == 0) ? h1i : ((s1 & 1) ? h1A : h1B);
                const float4* p1 = reinterpret_cast<const float4*>(src1);
                #pragma unroll
                for (int t = 0; t < 8; t++) {
                    int i = tid + t*256;
                    *reinterpret_cast<float4*>(&hs1[i << 2]) = __ldcg(p1 + i);
                }
            }
        }
        __syncthreads();

        if (r < SEQ) {
            float* dst0 = (r & 1) ? h0B : h0A;
            float hp0 = (l < 8) ? hs0[l*HID + j] : 0.f;

            unsigned long long ar[8], az[8], an[8];
            #pragma unroll
            for (int b = 0; b < 8; b++) { ar[b] = 0ull; az[b] = 0ull; an[b] = 0ull; }
            #pragma unroll
            for (int b = 0; b < 8; b++) {
                const float* hb = hs0 + b*HID;
                #pragma unroll
                for (int i = 0; i < 8; i++) {
                    ulonglong2 h2 = *reinterpret_cast<const ulonglong2*>(hb + i*128 + koff);
                    fma2(ar[b], h2.x, wr0[i].x);
                    fma2(ar[b], h2.y, wr0[i].y);
                    fma2(az[b], h2.x, wz0[i].x);
                    fma2(az[b], h2.y, wz0[i].y);
                    fma2(an[b], h2.x, wn0[i].x);
                    fma2(an[b], h2.y, wn0[i].y);
                }
            }
            #pragma unroll
            for (int b = 0; b < 8; b++) {
                float R  = wsum(hsum2(ar[b]));
                float Z  = wsum(hsum2(az[b]));
                float Nn = wsum(hsum2(an[b]));
                if (l == b) {
                    float rg   = 1.f / (1.f + __expf(-(pxr + R + br0)));
                    float zg   = 1.f / (1.f + __expf(-(pxz + Z + bz0)));
                    float ng   = tanhf(pxn + rg * (Nn + bn0));
                    float hnew = (1.f - zg) * ng + zg * hp0;
                    dst0[b*HID + j] = hnew;
                }
            }
        }

        if (r >= 1) {
            float* dst1 = (s1 & 1) ? h1B : h1A;
            float hp1 = (l < 8) ? hs1[l*HID + j] : 0.f;

            unsigned long long A[8], Bc[8], Cc[8], Dc[8];
            #pragma unroll
            for (int b = 0; b < 8; b++) { A[b]=0ull; Bc[b]=0ull; Cc[b]=0ull; Dc[b]=0ull; }

            const float* wsw = wsm + ((w*3) << 10);
            #pragma unroll 2
            for (int i = 0; i < 8; i++) {
                int k = i*128 + koff;
                ulonglong2 ur = *reinterpret_cast<const ulonglong2*>(wih1 + (size_t)(0*HID + j)*HID + k);
                ulonglong2 uz = *reinterpret_cast<const ulonglong2*>(wih1 + (size_t)(1*HID + j)*HID + k);
                ulonglong2 un = *reinterpret_cast<const ulonglong2*>(wih1 + (size_t)(2*HID + j)*HID + k);
                ulonglong2 vr = *reinterpret_cast<const ulonglong2*>(wsw + (0*8 + i)*128 + koff);
                ulonglong2 vz = *reinterpret_cast<const ulonglong2*>(wsw + (1*8 + i)*128 + koff);
                ulonglong2 vn = *reinterpret_cast<const ulonglong2*>(wsw + (2*8 + i)*128 + koff);
                #pragma unroll
                for (int b = 0; b < 8; b++) {
                    ulonglong2 yv = *reinterpret_cast<const ulonglong2*>(hs0 + b*HID + i*128 + koff);
                    ulonglong2 hv = *reinterpret_cast<const ulonglong2*>(hs1 + b*HID + i*128 + koff);
                    fma2(A[b],  yv.x, ur.x); fma2(A[b],  yv.y, ur.y);
                    fma2(A[b],  hv.x, vr.x); fma2(A[b],  hv.y, vr.y);
                    fma2(Bc[b], yv.x, uz.x); fma2(Bc[b], yv.y, uz.y);
                    fma2(Bc[b], hv.x, vz.x); fma2(Bc[b], hv.y, vz.y);
                    fma2(Cc[b], yv.x, un.x); fma2(Cc[b], yv.y, un.y);
                    fma2(Dc[b], hv.x, vn.x); fma2(Dc[b], hv.y, vn.y);
                }
            }
            #pragma unroll
            for (int b = 0; b < 8; b++) {
                float Av = wsum(hsum2(A[b]));
                float Bv = wsum(hsum2(Bc[b]));
                float Cv = wsum(hsum2(Cc[b]));
                float Dv = wsum(hsum2(Dc[b]));
                if (l == b) {
                    float rg   = 1.f / (1.f + __expf(-(Av + bA1)));
                    float zg   = 1.f / (1.f + __expf(-(Bv + bB1)));
                    float ng   = tanhf(Cv + bC1 + rg * (Dv + bD1));
                    float hnew = (1.f - zg) * ng + zg * hp1;
                    dst1[b*HID + j] = hnew;
                    y1[((size_t)b*SEQ + s1)*HID + j] = hnew;
                }
            }
        }

        if (l < 8 && r + 1 < SEQ) {
            size_t row = ((size_t)l*SEQ + (r + 1)) * GATES;
            pxr = __ldg(xg + row + j);
            pxz = __ldg(xg + row + HID + j);
            pxn = __ldg(xg + row + 2*HID + j);
        }

        if (r < SEQ) grid_sync();
    }
}

// ---------------- launcher -----------------------------------------------------
extern "C" void kernel_launch(void* const* d_in, const int* in_sizes, int n_in,
                              void* d_out, int out_size)
{
    (void)in_sizes; (void)n_in; (void)out_size;
    const float* concepts  = (const float*)d_in[0];
    const int*   seq       = (const int*)  d_in[1];
    const float* embedding = (const float*)d_in[2];
    const float* w_ih      = (const float*)d_in[3];
    const float* w_hh      = (const float*)d_in[4];
    const float* b_ih      = (const float*)d_in[5];
    const float* b_hh      = (const float*)d_in[6];
    const float* fc_w      = (const float*)d_in[7];
    const float* fc_b      = (const float*)d_in[8];
    const float* c2h_w     = (const float*)d_in[9];
    const float* c2h_b     = (const float*)d_in[10];
    float* out = (float*)d_out;

    float *xg, *y1, *h0i, *h0A, *h0B, *h1A, *h1B;
    cudaGetSymbolAddress((void**)&xg,  g_xg);
    cudaGetSymbolAddress((void**)&y1,  g_y1);
    cudaGetSymbolAddress((void**)&h0i, g_h0init);
    cudaGetSymbolAddress((void**)&h0A, g_h0A);
    cudaGetSymbolAddress((void**)&h0B, g_h0B);
    cudaGetSymbolAddress((void**)&h1A, g_h1A);
    cudaGetSymbolAddress((void**)&h1B, g_h1B);

    cudaFuncSetAttribute(gemm_bf16x3<true>,  cudaFuncAttributeMaxDynamicSharedMemorySize, GSMEM);
    cudaFuncSetAttribute(gemm_bf16x3<false>, cudaFuncAttributeMaxDynamicSharedMemorySize, GSMEM);
    cudaFuncSetAttribute(gru_fused, cudaFuncAttributeMaxDynamicSharedMemorySize, FUSED_SMEM);

    // 1) initial hidden states
    h0_kernel<<<BATCH, 256>>>(concepts, c2h_w, c2h_b);

    dim3 gx(MROWS/128, GATES/64);    // (32, 48)
    dim3 gl(MROWS/128, VOCAB/64);    // (32, 500)

    // 2) layer-0 input gates (embedding gather fused)
    gemm_bf16x3<true><<<gx, 256, GSMEM>>>(embedding, w_ih, b_ih, xg, seq,
                                          MROWS, GATES, HID);
    // 3) fused two-layer recurrence
    gru_fused<<<128, 256, FUSED_SMEM>>>(
        xg,
        w_hh, b_hh,
        w_ih + (size_t)GATES*HID, b_ih + GATES,
        w_hh + (size_t)GATES*HID, b_hh + GATES,
        h0i, h0i + BATCH*HID,
        y1, h0A, h0B, h1A, h1B);
    // 4) logits
    gemm_bf16x3<false><<<gl, 256, GSMEM>>>(y1, fc_w, fc_b, out, nullptr,
                                           MROWS, VOCAB, HID);
}

// round 13
// speedup vs baseline: 1.3994x; 1.2968x over previous
#include <cuda_runtime.h>
#include <cuda_bf16.h>
#include <math.h>

// Problem constants
#define HID    1024
#define VOCAB  32000
#define BATCH  8
#define SEQ    512
#define INDIM  768
#define MROWS  (BATCH*SEQ)      // 4096
#define GATES  (3*HID)          // 3072

// ---------------- scratch (no allocation allowed -> device globals) -----------
__device__ float g_h0init[2*BATCH*HID];      // [L][B][H]
__device__ float g_hA[BATCH*HID];
__device__ float g_hB[BATCH*HID];
__device__ float g_xg[(size_t)MROWS*GATES];  // input gates (reused per layer)
__device__ float g_y0[(size_t)MROWS*HID];
__device__ float g_y1[(size_t)MROWS*HID];
__device__ unsigned int          g_barcnt = 0;
__device__ volatile unsigned int g_bargen = 0;

// ---------------- h0: global context + c2h projection --------------------------
__global__ void h0_kernel(const float* __restrict__ concepts,
                          const float* __restrict__ c2h_w,
                          const float* __restrict__ c2h_b)
{
    __shared__ float ctx[INDIM];
    int b = blockIdx.x, tid = threadIdx.x;
    for (int d = tid; d < INDIM; d += blockDim.x) {
        float s = 0.f;
        #pragma unroll
        for (int n = 0; n < 16; n++) s += concepts[(b*16 + n)*INDIM + d];
        ctx[d] = s * (1.0f/16.0f);
    }
    __syncthreads();
    for (int k = tid; k < 2*HID; k += blockDim.x) {
        const float* w = c2h_w + (size_t)k*INDIM;
        float acc = 0.f;
        #pragma unroll 4
        for (int d = 0; d < INDIM; d += 4) {
            acc += ctx[d+0]*w[d+0] + ctx[d+1]*w[d+1]
                 + ctx[d+2]*w[d+2] + ctx[d+3]*w[d+3];
        }
        acc += c2h_b[k];
        int l = k >> 10, j = k & (HID-1);
        g_h0init[(l*BATCH + b)*HID + j] = acc;
    }
}

// ---------------- shared helpers ------------------------------------------------
__device__ __forceinline__ unsigned pack_bf2(float a, float b)
{
    __nv_bfloat162 t = __floats2bfloat162_rn(a, b);
    return *reinterpret_cast<unsigned*>(&t);
}

__device__ __forceinline__ void split_pair(float x, float y,
                                           unsigned& hi, unsigned& lo)
{
    hi = pack_bf2(x, y);
    __nv_bfloat162 hh = *reinterpret_cast<__nv_bfloat162*>(&hi);
    lo = pack_bf2(x - __bfloat162float(hh.x), y - __bfloat162float(hh.y));
}

__device__ __forceinline__ void mma_bf16(float* d, const unsigned* a, const unsigned* b)
{
    asm volatile(
        "mma.sync.aligned.m16n8k16.row.col.f32.bf16.bf16.f32 "
        "{%0,%1,%2,%3},{%4,%5,%6,%7},{%8,%9},{%0,%1,%2,%3};"
        : "+f"(d[0]), "+f"(d[1]), "+f"(d[2]), "+f"(d[3])
        : "r"(a[0]), "r"(a[1]), "r"(a[2]), "r"(a[3]), "r"(b[0]), "r"(b[1]));
}

__device__ __forceinline__ void ldsm_x4(unsigned* r, unsigned addr)
{
    asm volatile(
        "ldmatrix.sync.aligned.m8n8.x4.shared.b16 {%0,%1,%2,%3}, [%4];"
        : "=r"(r[0]), "=r"(r[1]), "=r"(r[2]), "=r"(r[3]) : "r"(addr));
}

__device__ __forceinline__ void ldsm_x2(unsigned* r, unsigned addr)
{
    asm volatile(
        "ldmatrix.sync.aligned.m8n8.x2.shared.b16 {%0,%1}, [%2];"
        : "=r"(r[0]), "=r"(r[1]) : "r"(addr));
}

// ---------------- bf16x3 tensor-core GEMM (R12, passing) -----------------------
#define GLDW  20
#define GTA   (128*GLDW)
#define GTB   (64*GLDW)
#define GBUF  (2*GTA + 2*GTB)
#define GSMEM (2*GBUF*4)

template<bool GATHER>
__global__ void __launch_bounds__(256, 2)
gemm_bf16x3(const float* __restrict__ A, const float* __restrict__ B,
            const float* __restrict__ bias, float* __restrict__ C,
            const int* __restrict__ gidx, int M, int N, int K)
{
    extern __shared__ unsigned sm[];
    const unsigned smb = (unsigned)__cvta_generic_to_shared(sm);
    const int tid = threadIdx.x;
    const int l   = tid & 31;
    const int wid = tid >> 5;
    const int wm  = (wid & 3) * 32;
    const int wn  = (wid >> 2) * 32;
    const int bm  = blockIdx.x * 128;
    const int bn  = blockIdx.y * 64;
    const int g   = l >> 2;
    const int t   = l & 3;
    const int lr  = l & 7;
    const int qA  = (l >> 3) & 1;
    const int qW  = (l >> 4);

    int aploc[4], bploc[2];
    const float* aptr[4];
    const float* bptr[2];
    #pragma unroll
    for (int u = 0; u < 4; u++) {
        int f    = tid + u*256;
        int row  = f >> 3;
        int kf   = (f & 7) << 2;
        aploc[u] = row*GLDW + ((f & 7) << 1);
        int ar   = GATHER ? gidx[bm + row] : (bm + row);
        aptr[u]  = A + (size_t)ar*K + kf;
    }
    #pragma unroll
    for (int u = 0; u < 2; u++) {
        int f    = tid + u*256;
        int row  = f >> 3;
        int kf   = (f & 7) << 2;
        bploc[u] = row*GLDW + ((f & 7) << 1);
        bptr[u]  = B + (size_t)(bn + row)*K + kf;
    }

    float acc[2][4][4];
    #pragma unroll
    for (int i = 0; i < 2; i++)
        #pragma unroll
        for (int jj = 0; jj < 4; jj++)
            #pragma unroll
            for (int r = 0; r < 4; r++) acc[i][jj][r] = 0.f;

    float4 va[4], vb[2];
    auto gload = [&](int kt) {
        #pragma unroll
        for (int u = 0; u < 4; u++)
            va[u] = *reinterpret_cast<const float4*>(aptr[u] + kt*32);
        #pragma unroll
        for (int u = 0; u < 2; u++)
            vb[u] = *reinterpret_cast<const float4*>(bptr[u] + kt*32);
    };
    auto sstore = [&](int buf) {
        unsigned* Ah = sm + buf*GBUF;
        unsigned* Al = Ah + GTA;
        unsigned* Bh = Al + GTA;
        unsigned* Bl = Bh + GTB;
        #pragma unroll
        for (int u = 0; u < 4; u++) {
            unsigned h0, l0, h1, l1;
            split_pair(va[u].x, va[u].y, h0, l0);
            split_pair(va[u].z, va[u].w, h1, l1);
            Ah[aploc[u]] = h0; Ah[aploc[u]+1] = h1;
            Al[aploc[u]] = l0; Al[aploc[u]+1] = l1;
        }
        #pragma unroll
        for (int u = 0; u < 2; u++) {
            unsigned h0, l0, h1, l1;
            split_pair(vb[u].x, vb[u].y, h0, l0);
            split_pair(vb[u].z, vb[u].w, h1, l1);
            Bh[bploc[u]] = h0; Bh[bploc[u]+1] = h1;
            Bl[bploc[u]] = l0; Bl[bploc[u]+1] = l1;
        }
    };

    const int nk = K / 32;
    gload(0); sstore(0); __syncthreads();

    for (int kt = 0; kt < nk; kt++) {
        int cur = kt & 1;
        if (kt + 1 < nk) gload(kt + 1);

        const unsigned AhB = smb + (cur*GBUF)*4u;
        const unsigned AlB = AhB + GTA*4u;
        const unsigned BhB = AlB + GTA*4u;
        const unsigned BlB = BhB + GTB*4u;

        #pragma unroll
        for (int kh = 0; kh < 2; kh++) {
            const int bp = kh * 8;
            unsigned ah[2][4], al[2][4], bh[4][2], bl[4][2];
            #pragma unroll
            for (int mf = 0; mf < 2; mf++) {
                unsigned aoff = (unsigned)((wm + mf*16 + qA*8 + lr)*GLDW
                                           + bp + (qW << 2)) * 4u;
                ldsm_x4(ah[mf], AhB + aoff);
                ldsm_x4(al[mf], AlB + aoff);
            }
            #pragma unroll
            for (int p = 0; p < 2; p++) {
                unsigned boff = (unsigned)((wn + (p*2 + qW)*8 + lr)*GLDW
                                           + bp + (((l >> 3) & 1) << 2)) * 4u;
                unsigned tmp[4];
                ldsm_x4(tmp, BhB + boff);
                bh[2*p][0] = tmp[0]; bh[2*p][1] = tmp[1];
                bh[2*p+1][0] = tmp[2]; bh[2*p+1][1] = tmp[3];
                ldsm_x4(tmp, BlB + boff);
                bl[2*p][0] = tmp[0]; bl[2*p][1] = tmp[1];
                bl[2*p+1][0] = tmp[2]; bl[2*p+1][1] = tmp[3];
            }
            #pragma unroll
            for (int mf = 0; mf < 2; mf++)
                #pragma unroll
                for (int nf = 0; nf < 4; nf++) {
                    mma_bf16(acc[mf][nf], ah[mf], bh[nf]);
                    mma_bf16(acc[mf][nf], ah[mf], bl[nf]);
                    mma_bf16(acc[mf][nf], al[mf], bh[nf]);
                }
        }
        if (kt + 1 < nk) sstore(cur ^ 1);
        __syncthreads();
    }

    #pragma unroll
    for (int mf = 0; mf < 2; mf++) {
        int row = bm + wm + mf*16 + g;
        #pragma unroll
        for (int nf = 0; nf < 4; nf++) {
            int col = bn + wn + nf*8 + (t << 1);
            float b0 = bias[col], b1 = bias[col+1];
            float2 v0 = make_float2(acc[mf][nf][0] + b0, acc[mf][nf][1] + b1);
            float2 v1 = make_float2(acc[mf][nf][2] + b0, acc[mf][nf][3] + b1);
            *reinterpret_cast<float2*>(C + (size_t)row*N + col)     = v0;
            *reinterpret_cast<float2*>(C + (size_t)(row+8)*N + col) = v1;
        }
    }
}

// ---------------- tensor-core GRU layer -----------------------------------------
// Block owns 8 j's -> 24 n-rows (r0..7, z0..7, n0..7) of whh. Per step:
// D[b=8, n=24] = h[8,1024] @ whh_blk[24,1024]^T via mma.m16n8k16 bf16x3.
// Warps K-split (8 ktiles each); partials reduced via smem; no shuffles.
// whh bf16 hi/lo resident in smem (prologue); h staged hi/lo each step.
#define BROW 516                 // padded words per 1024-col row (512 + 4)
#define OFF_BL 12384             // 24*516
#define OFF_AH 24768
#define OFF_AL 28896             // + 8*516
#define OFF_RED 33024            // + 8*516 ; red = 8 warps * 192 floats
#define GRU_SMEM ((OFF_RED + 1536) * 4)   // 138240 B

__device__ __forceinline__ void grid_sync()
{
    __threadfence();
    __syncthreads();
    if (threadIdx.x == 0) {
        unsigned int gen = g_bargen;
        if (atomicAdd(&g_barcnt, 1) == gridDim.x - 1) {
            g_barcnt = 0;
            __threadfence();
            g_bargen = gen + 1;
        } else {
            while (g_bargen == gen) { __nanosleep(64); }
        }
    }
    __syncthreads();
}

__global__ void __launch_bounds__(256, 1)
gru_tc(const float* __restrict__ xg,    // [B*SEQ, 3H], includes b_ih
       const float* __restrict__ whh,   // [3H, H]
       const float* __restrict__ bhh,   // [3H]
       const float* __restrict__ h0i,   // [B, H]
       float* __restrict__ y,           // [B, SEQ, H]
       float* hA, float* hB)
{
    extern __shared__ unsigned smw[];
    unsigned* Bh  = smw;
    unsigned* Bl  = smw + OFF_BL;
    unsigned* Ah  = smw + OFF_AH;
    unsigned* Al  = smw + OFF_AL;
    float*    red = reinterpret_cast<float*>(smw + OFF_RED);
    const unsigned smb = (unsigned)__cvta_generic_to_shared(smw);

    const int tid = threadIdx.x;
    const int w   = tid >> 5;
    const int l   = tid & 31;
    const int g   = l >> 2;          // mma row group 0..7
    const int t   = l & 3;
    const int i16 = l & 15;          // ldsm x2 address lane

    // prologue: whh block rows -> bf16 hi/lo smem [24][BROW]
    #pragma unroll 4
    for (int it = 0; it < 48; it++) {
        int wi   = tid + it*256;     // word id 0..12287
        int r24  = wi >> 9;
        int word = wi & 511;
        int grow = (r24 >> 3)*HID + blockIdx.x*8 + (r24 & 7);
        float2 v = *reinterpret_cast<const float2*>(whh + (size_t)grow*HID + word*2);
        unsigned hi, lo;
        split_pair(v.x, v.y, hi, lo);
        Bh[r24*BROW + word] = hi;
        Bl[r24*BROW + word] = lo;
    }
    __syncthreads();

    // gate-thread state (tid<64): b = tid&7, j = tid>>3
    const int gb = tid & 7, gj = tid >> 3;
    const int jg = blockIdx.x*8 + gj;
    float br = 0.f, bz = 0.f, bn_ = 0.f, pxr = 0.f, pxz = 0.f, pxn = 0.f;
    if (tid < 64) {
        br  = bhh[jg];
        bz  = bhh[HID + jg];
        bn_ = bhh[2*HID + jg];
        size_t row = ((size_t)gb*SEQ + 0) * GATES;
        pxr = __ldg(xg + row + jg);
        pxz = __ldg(xg + row + HID + jg);
        pxn = __ldg(xg + row + 2*HID + jg);
    }

    for (int s = 0; s < SEQ; s++) {
        const float* hsrc = (s == 0) ? h0i : ((s & 1) ? hA : hB);
        float*       hdst = (s & 1) ? hB : hA;

        // stage h -> A tiles (hi/lo), grab exact fp32 hprev for gate threads
        float hp = 0.f;
        if (tid < 64) hp = __ldcg(hsrc + gb*HID + jg);
        {
            const float4* h4 = reinterpret_cast<const float4*>(hsrc);
            #pragma unroll
            for (int it = 0; it < 8; it++) {
                int i = tid + it*256;            // float4 idx 0..2047
                float4 v = __ldcg(h4 + i);
                int row  = i >> 8;               // batch row 0..7
                int word = (i & 255) << 1;
                unsigned h0w, l0w, h1w, l1w;
                split_pair(v.x, v.y, h0w, l0w);
                split_pair(v.z, v.w, h1w, l1w);
                Ah[row*BROW + word]     = h0w;
                Ah[row*BROW + word + 1] = h1w;
                Al[row*BROW + word]     = l0w;
                Al[row*BROW + word + 1] = l1w;
            }
        }
        __syncthreads();

        // mma over this warp's 8 ktiles (K-split)
        float acc[3][4];
        #pragma unroll
        for (int p = 0; p < 3; p++)
            #pragma unroll
            for (int r = 0; r < 4; r++) acc[p][r] = 0.f;

        #pragma unroll 2
        for (int i = 0; i < 8; i++) {
            const int c  = w*8 + i;
            const int aw = c*8 + t;
            unsigned afh[4], afl[4];
            afh[0] = Ah[g*BROW + aw]; afh[1] = 0u;
            afh[2] = Ah[g*BROW + aw + 4]; afh[3] = 0u;
            afl[0] = Al[g*BROW + aw]; afl[1] = 0u;
            afl[2] = Al[g*BROW + aw + 4]; afl[3] = 0u;
            #pragma unroll
            for (int p = 0; p < 3; p++) {
                unsigned ro = (unsigned)((p*8 + (i16 & 7))*BROW + c*8 + ((i16 >> 3) << 2));
                unsigned bfh[2], bfl[2];
                ldsm_x2(bfh, smb + ro*4u);
                ldsm_x2(bfl, smb + (OFF_BL + ro)*4u);
                mma_bf16(acc[p], afh, bfh);   // hi*hi
                mma_bf16(acc[p], afh, bfl);   // hi*lo
                mma_bf16(acc[p], afl, bfh);   // lo*hi
            }
        }

        // store valid partials (rows 0..7 = c0,c1)
        #pragma unroll
        for (int p = 0; p < 3; p++) {
            red[w*192 + (p*8 + 2*t)*8 + g]     = acc[p][0];
            red[w*192 + (p*8 + 2*t + 1)*8 + g] = acc[p][1];
        }
        __syncthreads();

        // gates: reduce 8 warp-partials, pointwise, write h + y
        if (tid < 64) {
            float R = 0.f, Z = 0.f, Nn = 0.f;
            #pragma unroll
            for (int ww = 0; ww < 8; ww++) {
                R  += red[ww*192 + gj*8 + gb];
                Z  += red[ww*192 + (8 + gj)*8 + gb];
                Nn += red[ww*192 + (16 + gj)*8 + gb];
            }
            float rg   = 1.f / (1.f + __expf(-(pxr + R + br)));
            float zg   = 1.f / (1.f + __expf(-(pxz + Z + bz)));
            float ng   = tanhf(pxn + rg * (Nn + bn_));
            float hnew = (1.f - zg) * ng + zg * hp;
            hdst[gb*HID + jg] = hnew;
            y[((size_t)gb*SEQ + s)*HID + jg] = hnew;
            if (s + 1 < SEQ) {
                size_t row = ((size_t)gb*SEQ + (s + 1)) * GATES;
                pxr = __ldg(xg + row + jg);
                pxz = __ldg(xg + row + HID + jg);
                pxn = __ldg(xg + row + 2*HID + jg);
            }
        }
        if (s + 1 < SEQ) grid_sync();
    }
}

// ---------------- launcher -----------------------------------------------------
extern "C" void kernel_launch(void* const* d_in, const int* in_sizes, int n_in,
                              void* d_out, int out_size)
{
    (void)in_sizes; (void)n_in; (void)out_size;
    const float* concepts  = (const float*)d_in[0];
    const int*   seq       = (const int*)  d_in[1];
    const float* embedding = (const float*)d_in[2];
    const float* w_ih      = (const float*)d_in[3];
    const float* w_hh      = (const float*)d_in[4];
    const float* b_ih      = (const float*)d_in[5];
    const float* b_hh      = (const float*)d_in[6];
    const float* fc_w      = (const float*)d_in[7];
    const float* fc_b      = (const float*)d_in[8];
    const float* c2h_w     = (const float*)d_in[9];
    const float* c2h_b     = (const float*)d_in[10];
    float* out = (float*)d_out;

    float *xg, *y0, *y1, *h0i, *hA, *hB;
    cudaGetSymbolAddress((void**)&xg,  g_xg);
    cudaGetSymbolAddress((void**)&y0,  g_y0);
    cudaGetSymbolAddress((void**)&y1,  g_y1);
    cudaGetSymbolAddress((void**)&h0i, g_h0init);
    cudaGetSymbolAddress((void**)&hA,  g_hA);
    cudaGetSymbolAddress((void**)&hB,  g_hB);

    cudaFuncSetAttribute(gemm_bf16x3<true>,  cudaFuncAttributeMaxDynamicSharedMemorySize, GSMEM);
    cudaFuncSetAttribute(gemm_bf16x3<false>, cudaFuncAttributeMaxDynamicSharedMemorySize, GSMEM);
    cudaFuncSetAttribute(gru_tc, cudaFuncAttributeMaxDynamicSharedMemorySize, GRU_SMEM);

    // 1) initial hidden states
    h0_kernel<<<BATCH, 256>>>(concepts, c2h_w, c2h_b);

    dim3 gx(MROWS/128, GATES/64);    // (32, 48)
    dim3 gl(MROWS/128, VOCAB/64);    // (32, 500)

    // 2) layer-0 input gates (embedding gather fused)
    gemm_bf16x3<true><<<gx, 256, GSMEM>>>(embedding, w_ih, b_ih, xg, seq,
                                          MROWS, GATES, HID);
    // 3) layer-0 recurrence (tensor cores)
    gru_tc<<<128, 256, GRU_SMEM>>>(xg, w_hh, b_hh, h0i, y0, hA, hB);
    // 4) layer-1 input gates
    gemm_bf16x3<false><<<gx, 256, GSMEM>>>(y0, w_ih + (size_t)GATES*HID,
                                           b_ih + GATES, xg, nullptr,
                                           MROWS, GATES, HID);
    // 5) layer-1 recurrence (tensor cores)
    gru_tc<<<128, 256, GRU_SMEM>>>(xg, w_hh + (size_t)GATES*HID, b_hh + GATES,
                                   h0i + BATCH*HID, y1, hA, hB);
    // 6) logits
    gemm_bf16x3<false><<<gl, 256, GSMEM>>>(y1, fc_w, fc_b, out, nullptr,
                                           MROWS, VOCAB, HID);
}